// round 12
// baseline (speedup 1.0000x reference)
#include <cuda_runtime.h>
#include <cuda_bf16.h>
#include <cstdint>

// Problem constants (B=32, T=2048, D_IN=1024, H1=512, H2=32)
#define NB_   32
#define T_    2048
#define DIN   1024
#define H1_   512
#define ROWS  (NB_ * T_)   // 65536

// GEMM tiling: CTA = 128 x 256, 256 threads (8 warps as 4Mx2N, warp tile 32x128)
#define MTILE 128
#define NTILE 256
#define KC    64           // K (fp8 elems) per smem stage
#define NSTG  (DIN / KC)   // 16 stages

// 16B-aligned row strides (cp.async/ldmatrix need 16B alignment!)
// 80 mod 128: chunk index (5r+c) mod 8 distinct over 8 rows -> conflict-free ldmatrix
#define A_STR 80           // bytes per A smem row (64B data + 16 pad)
#define B_STR 80           // bytes per B smem row (n-major, 64B k data + 16 pad)

#define SCALE_W   64.0f    // W1 scaled into e4m3 normal range
#define INV_SCALE (1.0f / 64.0f)

// ---------------- device scratch ----------------
__device__ uint8_t g_w1q[H1_ * DIN];      // W1 e4m3, TRANSPOSED [n][k], pre-scaled by 64
__device__ float   g_weff[H1_];           // W2 @ W3
__device__ float   g_beff;                // b2 . W3 + b3
__device__ float   g_zpart[2][ROWS];      // per-N-half partial pre-sigmoid logits

// ---------------- kernel 0: prep ----------------
// g_w1q[n][k] = e4m3(64 * W1[k][n]); coalesced reads of W1, u16 writes (L2-resident 512KB)
__global__ void prep_kernel(const float* __restrict__ W1,
                            const float* __restrict__ W2,
                            const float* __restrict__ b2,
                            const float* __restrict__ W3,
                            const float* __restrict__ b3) {
    int gid    = blockIdx.x * blockDim.x + threadIdx.x;
    int stride = gridDim.x * blockDim.x;
    uint16_t* out = reinterpret_cast<uint16_t*>(g_w1q);
    // gid indexes (kp, n): kp = k/2 in [0,512), n in [0,512)
    for (int i = gid; i < (DIN / 2) * H1_; i += stride) {
        int kp = i >> 9;            // k pair index
        int n  = i & (H1_ - 1);
        float v0 = W1[(size_t)(2 * kp)     * H1_ + n] * SCALE_W;
        float v1 = W1[(size_t)(2 * kp + 1) * H1_ + n] * SCALE_W;
        uint16_t p;                 // hi byte = src1 (v1), lo byte = src2 (v0) -> k order
        asm("cvt.rn.satfinite.e4m3x2.f32 %0, %1, %2;" : "=h"(p) : "f"(v1), "f"(v0));
        out[(size_t)n * (DIN / 2) + kp] = p;
    }
    if (gid < H1_) {
        float s = 0.f;
        #pragma unroll
        for (int c = 0; c < 32; ++c) s += W2[gid * 32 + c] * W3[c];
        g_weff[gid] = s;
    }
    if (gid == 0) {
        float s = b3[0];
        #pragma unroll
        for (int c = 0; c < 32; ++c) s += b2[c] * W3[c];
        g_beff = s;
    }
}

// ---------------- kernel 1: fp8 GEMM + bias + relu + weff-dot ----------------
struct __align__(16) Smem {
    uint8_t As[2][MTILE][A_STR];   // 20480 B
    uint8_t Bs[2][NTILE][B_STR];   // 40960 B
    float b1s[NTILE];              //  1024 B  (pre-scaled by 64)
    float wsm[NTILE];              //  1024 B  (pre-scaled by 1/64)
    float zs[MTILE];               //   512 B
};                                 // ~64 KB

__global__ __launch_bounds__(256, 1)
void mlp_gemm_kernel(const float* __restrict__ A, const float* __restrict__ b1) {
    extern __shared__ char smem_raw[];
    Smem& sm = *reinterpret_cast<Smem*>(smem_raw);

    const int tid  = threadIdx.x;
    const int lane = tid & 31;
    const int warp = tid >> 5;
    const int wm   = warp >> 1;   // 0..3  (M groups of 32 rows)
    const int wn   = warp & 1;    // 0..1  (N groups of 128 cols)

    const int nt_blk   = blockIdx.x & 1;     // which 256-col half of H1
    const int row_tile = blockIdx.x >> 1;    // 0..511
    const int row_base = row_tile * MTILE;
    const int n_base   = nt_blk * NTILE;

    sm.b1s[tid] = b1[n_base + tid] * SCALE_W;
    sm.wsm[tid] = g_weff[n_base + tid] * INV_SCALE;
    if (tid < MTILE) sm.zs[tid] = 0.f;

    float acc[2][16][4];
    #pragma unroll
    for (int a = 0; a < 2; ++a)
        #pragma unroll
        for (int b = 0; b < 16; ++b)
            #pragma unroll
            for (int c = 0; c < 4; ++c) acc[a][b][c] = 0.f;

    const float*   Ab = A + (size_t)row_base * DIN;
    const uint8_t* Bb = g_w1q + (size_t)n_base * DIN;

    const uint32_t as_u = (uint32_t)__cvta_generic_to_shared(&sm.As[0][0][0]);
    const uint32_t bs_u = (uint32_t)__cvta_generic_to_shared(&sm.Bs[0][0][0]);
    const uint32_t AS_BUF = MTILE * A_STR;
    const uint32_t BS_BUF = NTILE * B_STR;

    // A staging: thread handles row tid>>1, 32-float half tid&1
    const int r_a = tid >> 1;
    const int h_a = tid & 1;
    float4 ar[8];                  // 32 floats live across compute

    auto ldgA = [&](int s) {
        const float* rp = Ab + (size_t)r_a * DIN + s * KC + h_a * 32;
        #pragma unroll
        for (int i = 0; i < 8; ++i)
            ar[i] = *reinterpret_cast<const float4*>(rp + i * 4);
    };
    auto stsA = [&](int buf) {     // fp32 -> e4m3 (x4 packed) -> smem
        uint32_t q[8];
        #pragma unroll
        for (int i = 0; i < 8; ++i) {
            uint16_t plo, phi;     // lo byte = earlier k
            asm("cvt.rn.satfinite.e4m3x2.f32 %0, %1, %2;" : "=h"(plo) : "f"(ar[i].y), "f"(ar[i].x));
            asm("cvt.rn.satfinite.e4m3x2.f32 %0, %1, %2;" : "=h"(phi) : "f"(ar[i].w), "f"(ar[i].z));
            q[i] = (uint32_t)plo | ((uint32_t)phi << 16);
        }
        const uint32_t base = as_u + buf * AS_BUF + (uint32_t)(r_a * A_STR + h_a * 32);
        #pragma unroll
        for (int j = 0; j < 4; ++j)
            asm volatile("st.shared.v2.b32 [%0], {%1,%2};"
                         :: "r"(base + j * 8), "r"(q[2 * j]), "r"(q[2 * j + 1]));
    };
    auto loadB = [&](int buf, int s) {   // 256 n-rows x 64B via cp.async (4 x 16B / thread)
        const int k0 = s * KC;
        #pragma unroll
        for (int j = 0; j < 4; ++j) {
            int lin = tid + j * 256;                 // 0..1023
            int n   = lin >> 2;                      // 0..255
            int c   = lin & 3;                       // 16B chunk
            uint32_t dst = bs_u + buf * BS_BUF + (uint32_t)(n * B_STR + c * 16);
            const void* src = Bb + (size_t)n * DIN + k0 + c * 16;
            asm volatile("cp.async.cg.shared.global [%0], [%1], 16;" :: "r"(dst), "l"(src));
        }
        asm volatile("cp.async.commit_group;");
    };
    auto compute = [&](int buf) {
        const uint32_t abase = as_u + buf * AS_BUF;
        const uint32_t bbase = bs_u + buf * BS_BUF;
        const int lr = lane & 15;      // row within 16 (m for A, n for B)
        const int lc = lane >> 4;      // 16B k-chunk select
        #pragma unroll
        for (int ks = 0; ks < 2; ++ks) {           // two K32 steps per stage
            uint32_t a_reg[2][4];
            #pragma unroll
            for (int mt = 0; mt < 2; ++mt) {
                uint32_t addr = abase
                    + (uint32_t)((wm * 32 + mt * 16 + lr) * A_STR + ks * 32 + lc * 16);
                asm volatile("ldmatrix.sync.aligned.m8n8.x4.shared.b16 {%0,%1,%2,%3}, [%4];"
                             : "=r"(a_reg[mt][0]), "=r"(a_reg[mt][1]),
                               "=r"(a_reg[mt][2]), "=r"(a_reg[mt][3]) : "r"(addr));
            }
            uint32_t b_reg[16][2];
            #pragma unroll
            for (int nb = 0; nb < 8; ++nb) {       // n16 group, k32: x4 NON-trans on [n][k]
                uint32_t addr = bbase
                    + (uint32_t)((wn * 128 + nb * 16 + lr) * B_STR + ks * 32 + lc * 16);
                uint32_t r0, r1, r2, r3;
                asm volatile("ldmatrix.sync.aligned.m8n8.x4.shared.b16 {%0,%1,%2,%3}, [%4];"
                             : "=r"(r0), "=r"(r1), "=r"(r2), "=r"(r3) : "r"(addr));
                // tiles: r0=(n lo8,k lo) r1=(n hi8,k lo) r2=(n lo8,k hi) r3=(n hi8,k hi)
                b_reg[nb * 2][0]     = r0; b_reg[nb * 2][1]     = r2;
                b_reg[nb * 2 + 1][0] = r1; b_reg[nb * 2 + 1][1] = r3;
            }
            #pragma unroll
            for (int mt = 0; mt < 2; ++mt)
                #pragma unroll
                for (int nt = 0; nt < 16; ++nt) {
                    asm volatile(
                        "mma.sync.aligned.m16n8k32.row.col.f32.e4m3.e4m3.f32 "
                        "{%0,%1,%2,%3}, {%4,%5,%6,%7}, {%8,%9}, {%0,%1,%2,%3};"
                        : "+f"(acc[mt][nt][0]), "+f"(acc[mt][nt][1]),
                          "+f"(acc[mt][nt][2]), "+f"(acc[mt][nt][3])
                        : "r"(a_reg[mt][0]), "r"(a_reg[mt][1]),
                          "r"(a_reg[mt][2]), "r"(a_reg[mt][3]),
                          "r"(b_reg[nt][0]), "r"(b_reg[nt][1]));
                }
        }
    };

    // ---- prologue ----
    ldgA(0);
    loadB(0, 0);
    stsA(0);
    asm volatile("cp.async.wait_group 0;");
    __syncthreads();

    // ---- pipelined main loop ----
    for (int s = 0; s < NSTG; ++s) {
        const int buf = s & 1;
        if (s + 1 < NSTG) {
            ldgA(s + 1);            // DRAM latency hidden behind compute(s)
            loadB(buf ^ 1, s + 1);
        }
        compute(buf);
        if (s + 1 < NSTG) stsA(buf ^ 1);
        asm volatile("cp.async.wait_group 0;");
        __syncthreads();
    }

    // ---- epilogue: (acc + 64*b1) relu, dot with weff/64, reduce per row ----
    const int g = lane >> 2, tig = lane & 3;
    #pragma unroll
    for (int mt = 0; mt < 2; ++mt) {
        float sa = 0.f, sb = 0.f;
        #pragma unroll
        for (int nt = 0; nt < 16; ++nt) {
            int c0 = wn * 128 + nt * 8 + tig * 2;
            float w0 = sm.wsm[c0],  w1 = sm.wsm[c0 + 1];
            float q0 = sm.b1s[c0],  q1 = sm.b1s[c0 + 1];
            float h0 = fmaxf(acc[mt][nt][0] + q0, 0.f);
            float h1 = fmaxf(acc[mt][nt][1] + q1, 0.f);
            float h2 = fmaxf(acc[mt][nt][2] + q0, 0.f);
            float h3 = fmaxf(acc[mt][nt][3] + q1, 0.f);
            sa += h0 * w0 + h1 * w1;
            sb += h2 * w0 + h3 * w1;
        }
        sa += __shfl_xor_sync(0xffffffffu, sa, 1);
        sa += __shfl_xor_sync(0xffffffffu, sa, 2);
        sb += __shfl_xor_sync(0xffffffffu, sb, 1);
        sb += __shfl_xor_sync(0xffffffffu, sb, 2);
        if (tig == 0) {
            atomicAdd(&sm.zs[wm * 32 + mt * 16 + g], sa);
            atomicAdd(&sm.zs[wm * 32 + mt * 16 + g + 8], sb);
        }
    }
    __syncthreads();
    if (tid < MTILE)
        g_zpart[nt_blk][row_base + tid] = sm.zs[tid];
}

// ---------------- kernel 2: per-sample sigmoid + ragged top-k mean ----------------
__global__ void topk_kernel(const int* __restrict__ seq_len, float* __restrict__ out) {
    __shared__ float s[T_];
    __shared__ float red[8];
    const int b   = blockIdx.x;
    const int tid = threadIdx.x;
    const int L   = seq_len[b];
    const float beff = g_beff;

    for (int i = tid; i < T_; i += blockDim.x) {
        float v = -1.0f;  // below sigmoid range -> never in top-k
        if (i < L) {
            float z = g_zpart[0][b * T_ + i] + g_zpart[1][b * T_ + i] + beff;
            v = 1.0f / (1.0f + expf(-z));
        }
        s[i] = v;
    }
    __syncthreads();

    // bitonic sort, descending
    for (int size = 2; size <= T_; size <<= 1) {
        for (int stride = size >> 1; stride > 0; stride >>= 1) {
            for (int i = tid; i < T_; i += blockDim.x) {
                int j = i ^ stride;
                if (j > i) {
                    bool desc = ((i & size) == 0);
                    float x = s[i], y = s[j];
                    if ((x < y) == desc) { s[i] = y; s[j] = x; }
                }
            }
            __syncthreads();
        }
    }

    const int k = L / 16 + 1;   // k <= L always
    float p = 0.f;
    for (int i = tid; i < k; i += blockDim.x) p += s[i];
    p += __shfl_xor_sync(0xffffffffu, p, 16);
    p += __shfl_xor_sync(0xffffffffu, p, 8);
    p += __shfl_xor_sync(0xffffffffu, p, 4);
    p += __shfl_xor_sync(0xffffffffu, p, 2);
    p += __shfl_xor_sync(0xffffffffu, p, 1);
    if ((tid & 31) == 0) red[tid >> 5] = p;
    __syncthreads();
    if (tid == 0) {
        float sum = 0.f;
        #pragma unroll
        for (int w = 0; w < 8; ++w) sum += red[w];
        out[b] = sum / (float)k;
    }
}

// ---------------- entry point ----------------
// Inputs: 0 avf_out [32,2048,1024] f32; 1 W1 [1024,512]; 2 b1 [512]; 3 W2 [512,32];
//         4 b2 [32]; 5 W3 [32,1]; 6 b3 [1]; 7 seq_len [32] i32. Output: [32] f32.
extern "C" void kernel_launch(void* const* d_in, const int* in_sizes, int n_in,
                              void* d_out, int out_size) {
    const float* avf = (const float*)d_in[0];
    const float* W1  = (const float*)d_in[1];
    const float* b1  = (const float*)d_in[2];
    const float* W2  = (const float*)d_in[3];
    const float* b2  = (const float*)d_in[4];
    const float* W3  = (const float*)d_in[5];
    const float* b3  = (const float*)d_in[6];
    const int*   seq = (const int*)d_in[7];
    float*       out = (float*)d_out;

    cudaFuncSetAttribute(mlp_gemm_kernel,
                         cudaFuncAttributeMaxDynamicSharedMemorySize,
                         (int)sizeof(Smem));

    prep_kernel<<<512, 256>>>(W1, W2, b2, W3, b3);
    mlp_gemm_kernel<<<(ROWS / MTILE) * (H1_ / NTILE), 256, sizeof(Smem)>>>(avf, b1);
    topk_kernel<<<NB_, 256>>>(seq, out);
}